// round 6
// baseline (speedup 1.0000x reference)
#include <cuda_runtime.h>
#include <math.h>

#define NN      50000
#define NE      800000
#define NHEADS  4
#define NHID    64
#define NHC     256

// ---------------- scratch (static device globals; no allocation) ----------------
__device__ __align__(16) float g_XL  [(size_t)NN * NHC];    // 51.2 MB
__device__ __align__(16) float g_XR  [(size_t)NN * NHC];    // 51.2 MB
__device__ __align__(16) float g_ACCH[(size_t)NN * NHC];    // 51.2 MB per-head raw sums
__device__ __align__(16) float g_DEN [(size_t)NN * NHEADS]; // 0.8 MB  softmax denominators
__device__ __align__(16) float g_A   [(size_t)NN * NHID];   // 12.8 MB layer input
__device__ __align__(16) int   g_SRC[NE];
__device__ __align__(16) int   g_DST[NE];

// ---------------- canonicalize edge_index (handles int32 OR int64 input) -------
__global__ void k_convert(const void* __restrict__ ei_raw) {
    __shared__ int s_is64;
    const int* ei32 = (const int*)ei_raw;
    if (threadIdx.x == 0) {
        int nz = 0;
#pragma unroll
        for (int i = 0; i < 32; i++) nz |= ei32[2 * i + 1];
        s_is64 = (nz == 0);
    }
    __syncthreads();
    int e = blockIdx.x * 256 + threadIdx.x;   // grid covers exactly NE
    if (s_is64) {
        const long long* ei64 = (const long long*)ei_raw;
        g_SRC[e] = (int)ei64[e];
        g_DST[e] = (int)ei64[NE + e];
    } else {
        g_SRC[e] = ei32[e];
        g_DST[e] = ei32[NE + e];
    }
}

// ---------------- zero accumulators + denominators (float4) ----------------
__global__ void k_zero() {
    int i = blockIdx.x * 256 + threadIdx.x;   // grid covers NN*NHC/4 = 3.2M
    const float4 z = make_float4(0.f, 0.f, 0.f, 0.f);
    *(float4*)&g_ACCH[(size_t)i * 4] = z;
    if (i < NN) *(float4*)&g_DEN[(size_t)i * 4] = z;   // NN*4 denominators
}

// ---------------- dual GEMM: O = A[M,K] @ W[K,256] + b ----------------
template <int K>
__global__ __launch_bounds__(256) void k_gemm(
    const float* __restrict__ Aext, int useA,
    const float* __restrict__ W1, const float* __restrict__ b1,
    const float* __restrict__ W2, const float* __restrict__ b2)
{
    const float* A = useA ? g_A : Aext;
    const float* W = blockIdx.z ? W2 : W1;
    const float* b = blockIdx.z ? b2 : b1;
    float*       O = blockIdx.z ? g_XR : g_XL;

    const int m0 = blockIdx.y * 128;
    const int n0 = blockIdx.x * 128;

    __shared__ __align__(16) float sA[128][20];
    __shared__ __align__(16) float sW[16][132];

    const int tid = threadIdx.x;
    const int ty = tid >> 4, tx = tid & 15;

    float acc[8][8];
#pragma unroll
    for (int i = 0; i < 8; i++)
#pragma unroll
        for (int j = 0; j < 8; j++) acc[i][j] = 0.f;

    for (int kt = 0; kt < K; kt += 16) {
#pragma unroll
        for (int u = 0; u < 2; u++) {
            int slot = tid + u * 256;
            int row = slot >> 2, ch = slot & 3;
            int gr = m0 + row;
            float4 v = make_float4(0.f, 0.f, 0.f, 0.f);
            if (gr < NN) v = *(const float4*)(A + (size_t)gr * K + kt + ch * 4);
            *(float4*)&sA[row][ch * 4] = v;
        }
#pragma unroll
        for (int u = 0; u < 2; u++) {
            int slot = tid + u * 256;
            int kk = slot >> 5, nc = (slot & 31) * 4;
            float4 v = *(const float4*)(W + (size_t)(kt + kk) * NHC + n0 + nc);
            *(float4*)&sW[kk][nc] = v;
        }
        __syncthreads();

#pragma unroll
        for (int kk = 0; kk < 16; kk++) {
            float a[8];
#pragma unroll
            for (int i = 0; i < 8; i++) a[i] = sA[ty * 8 + i][kk];
            float4 w0 = *(float4*)&sW[kk][tx * 8];
            float4 w1 = *(float4*)&sW[kk][tx * 8 + 4];
            float w[8] = {w0.x, w0.y, w0.z, w0.w, w1.x, w1.y, w1.z, w1.w};
#pragma unroll
            for (int i = 0; i < 8; i++)
#pragma unroll
                for (int j = 0; j < 8; j++)
                    acc[i][j] = fmaf(a[i], w[j], acc[i][j]);
        }
        __syncthreads();
    }

    float4 bv0 = *(const float4*)(b + n0 + tx * 8);
    float4 bv1 = *(const float4*)(b + n0 + tx * 8 + 4);
#pragma unroll
    for (int i = 0; i < 8; i++) {
        int gr = m0 + ty * 8 + i;
        if (gr < NN) {
            float4 o0 = make_float4(acc[i][0] + bv0.x, acc[i][1] + bv0.y,
                                    acc[i][2] + bv0.z, acc[i][3] + bv0.w);
            float4 o1 = make_float4(acc[i][4] + bv1.x, acc[i][5] + bv1.y,
                                    acc[i][6] + bv1.z, acc[i][7] + bv1.w);
            float* op = O + (size_t)gr * NHC + n0 + tx * 8;
            *(float4*)op = o0;
            *(float4*)(op + 4) = o1;
        }
    }
}

// ---------------- fused edge pass ----------------
// 64 threads per edge, 4 channels per thread (float4), 4 edges per 256-block.
// Computes logit -> p = exp(logit); scatters p (denominators) and p*xl
// (unnormalized per-head message sums). Normalization happens in k_node.
__global__ __launch_bounds__(256) void k_edge(
    const float* __restrict__ ea,
    const float* __restrict__ We, const float* __restrict__ att)
{
    const int tid    = threadIdx.x;
    const int e_loc  = tid >> 6;          // 0..3
    const int quad   = tid & 63;          // 0..63 -> channels quad*4..+3
    const int ch0    = quad * 4;
    const int head   = quad >> 4;         // 0..3

    // per-thread constants: We[9][4ch] and att[4ch]
    float4 we4[9];
#pragma unroll
    for (int k = 0; k < 9; k++) we4[k] = *(const float4*)(We + k * NHC + ch0);
    const float4 att4 = *(const float4*)(att + ch0);

    __shared__ float sea[4][12];          // padded rows (48B, 16B-aligned)

    for (int ebase = blockIdx.x * 4; ebase < NE; ebase += gridDim.x * 4) {
        __syncthreads();   // protect sea across iterations
        if (tid < 36) sea[tid / 9][tid % 9] = ea[(size_t)(ebase + tid / 9) * 9 + tid % 9];

        const int e   = ebase + e_loc;
        const int src = g_SRC[e];
        const int dst = g_DST[e];

        const float4 xl4 = *(const float4*)(g_XL + (size_t)src * NHC + ch0);
        const float4 xr4 = *(const float4*)(g_XR + (size_t)dst * NHC + ch0);
        __syncthreads();   // sea ready

        // edge projection for this thread's 4 channels
        float4 ev = make_float4(0.f, 0.f, 0.f, 0.f);
#pragma unroll
        for (int k = 0; k < 9; k++) {
            const float a = sea[e_loc][k];
            ev.x = fmaf(we4[k].x, a, ev.x);
            ev.y = fmaf(we4[k].y, a, ev.y);
            ev.z = fmaf(we4[k].z, a, ev.z);
            ev.w = fmaf(we4[k].w, a, ev.w);
        }
        float mx = xl4.x + xr4.x + ev.x;
        float my = xl4.y + xr4.y + ev.y;
        float mz = xl4.z + xr4.z + ev.z;
        float mw = xl4.w + xr4.w + ev.w;
        // leaky_relu(0.2) then dot with att
        mx = (mx > 0.f) ? mx : 0.2f * mx;
        my = (my > 0.f) ? my : 0.2f * my;
        mz = (mz > 0.f) ? mz : 0.2f * mz;
        mw = (mw > 0.f) ? mw : 0.2f * mw;
        float part = att4.x * mx;
        part = fmaf(att4.y, my, part);
        part = fmaf(att4.z, mz, part);
        part = fmaf(att4.w, mw, part);

        // reduce over the 16 lanes of this head (width-16 groups)
        part += __shfl_down_sync(0xffffffffu, part, 8, 16);
        part += __shfl_down_sync(0xffffffffu, part, 4, 16);
        part += __shfl_down_sync(0xffffffffu, part, 2, 16);
        part += __shfl_down_sync(0xffffffffu, part, 1, 16);
        const float logit = __shfl_sync(0xffffffffu, part, 0, 16);
        const float p = __expf(logit);

        if ((quad & 15) == 0)
            atomicAdd(&g_DEN[(size_t)dst * NHEADS + head], p);

        float4 msg = make_float4(xl4.x * p, xl4.y * p, xl4.z * p, xl4.w * p);
        atomicAdd((float4*)(g_ACCH + (size_t)dst * NHC + ch0), msg);
    }
}

// ---------------- node update: normalize, head-mean, bias, gating ----------------
__global__ void k_node(const float* __restrict__ bias, const float* __restrict__ gates,
                       int layer, float* __restrict__ out) {
    int i = blockIdx.x * 256 + threadIdx.x;   // grid covers exactly NN*NHID
    int n = i >> 6, c = i & 63;
    const float* accn = g_ACCH + (size_t)n * NHC;
    const float* denn = g_DEN + (size_t)n * NHEADS;
    float val = 0.f;
#pragma unroll
    for (int h = 0; h < NHEADS; h++)
        val = fmaf(accn[h * NHID + c], __fdividef(0.25f, denn[h] + 1e-16f), val);
    val += bias[c];
    if (layer == 0) {
        g_A[i] = (val > 0.f) ? val : 0.01f * val;
    } else {
        float g = 1.f / (1.f + __expf(-gates[layer - 1]));
        float h = g * val + (1.f - g) * g_A[i];
        if (layer == 1) g_A[i] = (h > 0.f) ? h : 0.01f * h;
        else            out[i] = h;
    }
}

// ---------------- host ----------------
extern "C" void kernel_launch(void* const* d_in, const int* in_sizes, int n_in,
                              void* d_out, int out_size) {
    (void)out_size;
    const float *x = 0, *edge_attr = 0, *gates = 0;
    const float *W32k[4] = {0, 0, 0, 0};  int n32k = 0;   // init_Wl, init_Wr, Wl, Wr
    const float *a256[3] = {0, 0, 0};     int n256 = 0;   // init_bl, init_br, init_att
    const float *a512[3] = {0, 0, 0};     int n512 = 0;   // bl, br, att
    const float *init_We = 0, *WeL = 0, *init_bias = 0, *biasL = 0;
    const void* ei = 0;

    for (int i = 0; i < n_in; i++) {
        const void* p = d_in[i];
        switch (in_sizes[i]) {
            case 6400000: x = (const float*)p; break;
            case 7200000: edge_attr = (const float*)p; break;
            case 1600000: ei = p; break;
            case 3:       gates = (const float*)p; break;
            case 32768:   if (n32k < 4) W32k[n32k++] = (const float*)p; break;
            case 256:     if (n256 < 3) a256[n256++] = (const float*)p; break;
            case 512:     if (n512 < 3) a512[n512++] = (const float*)p; break;
            case 2304:    init_We = (const float*)p; break;
            case 4608:    WeL = (const float*)p; break;
            case 64:      init_bias = (const float*)p; break;
            case 128:     biasL = (const float*)p; break;
            default: break;
        }
    }
    const float *Wl0 = W32k[0], *Wr0 = W32k[1], *WlL = W32k[2], *WrL = W32k[3];
    const float *bl0 = a256[0], *br0 = a256[1], *att0 = a256[2];
    const float *blL = a512[0], *brL = a512[1], *attL = a512[2];
    float* out = (float*)d_out;

    k_convert<<<NE / 256, 256>>>(ei);

    const dim3 gemm_grid(2, (NN + 127) / 128, 2);

    for (int l = 0; l < 3; l++) {
        k_zero<<<NN * NHC / 4 / 256, 256>>>();

        if (l == 0) {
            k_gemm<128><<<gemm_grid, 256>>>(x, 0, Wl0, bl0, Wr0, br0);
        } else {
            const float* Wl = WlL + (size_t)(l - 1) * 64 * 256;
            const float* Wr = WrL + (size_t)(l - 1) * 64 * 256;
            const float* bl = blL + (size_t)(l - 1) * 256;
            const float* br = brL + (size_t)(l - 1) * 256;
            k_gemm<64><<<gemm_grid, 256>>>(0, 1, Wl, bl, Wr, br);
        }

        const float* We  = l ? (WeL  + (size_t)(l - 1) * 9 * 256) : init_We;
        const float* att = l ? (attL + (size_t)(l - 1) * 256)     : att0;

        k_edge<<<2368, 256>>>(edge_attr, We, att);

        const float* bias = l ? (biasL + (size_t)(l - 1) * 64) : init_bias;
        k_node<<<NN * NHID / 256, 256>>>(bias, gates, l, out);
    }
}

// round 7
// speedup vs baseline: 1.1923x; 1.1923x over previous
#include <cuda_runtime.h>
#include <math.h>

#define NN      50000
#define NE      800000
#define NHEADS  4
#define NHID    64
#define NHC     256

// ---------------- scratch (static device globals; no allocation) ----------------
__device__ __align__(16) float g_XL [(size_t)NN * NHC];    // 51.2 MB
__device__ __align__(16) float g_XR [(size_t)NN * NHC];    // 51.2 MB
__device__ __align__(16) float g_P  [(size_t)NE * NHEADS]; // 12.8 MB exp(logit)
__device__ __align__(16) float g_DEN[(size_t)NN * NHEADS]; // 0.8 MB  denom -> 0.25/(d+eps)
__device__ __align__(16) float g_ACC[(size_t)NN * NHID];   // 12.8 MB head-mean messages
__device__ __align__(16) float g_A  [(size_t)NN * NHID];   // 12.8 MB layer input
__device__ __align__(16) int   g_SRC[NE];
__device__ __align__(16) int   g_DST[NE];

// ---------------- canonicalize edge_index (handles int32 OR int64 input) -------
__global__ void k_convert(const void* __restrict__ ei_raw) {
    __shared__ int s_is64;
    const int* ei32 = (const int*)ei_raw;
    if (threadIdx.x == 0) {
        int nz = 0;
#pragma unroll
        for (int i = 0; i < 32; i++) nz |= ei32[2 * i + 1];
        s_is64 = (nz == 0);
    }
    __syncthreads();
    int e = blockIdx.x * 256 + threadIdx.x;   // grid covers exactly NE
    if (s_is64) {
        const long long* ei64 = (const long long*)ei_raw;
        g_SRC[e] = (int)ei64[e];
        g_DST[e] = (int)ei64[NE + e];
    } else {
        g_SRC[e] = ei32[e];
        g_DST[e] = ei32[NE + e];
    }
}

// ---------------- zero accumulators + denominators ----------------
__global__ void k_zero() {
    int i = blockIdx.x * 256 + threadIdx.x;   // grid covers exactly NN*NHID
    g_ACC[i] = 0.f;
    if (i < NN * NHEADS) g_DEN[i] = 0.f;
}

// ---------------- dual GEMM: O = A[M,K] @ W[K,256] + b ----------------
template <int K>
__global__ __launch_bounds__(256) void k_gemm(
    const float* __restrict__ Aext, int useA,
    const float* __restrict__ W1, const float* __restrict__ b1,
    const float* __restrict__ W2, const float* __restrict__ b2)
{
    const float* A = useA ? g_A : Aext;
    const float* W = blockIdx.z ? W2 : W1;
    const float* b = blockIdx.z ? b2 : b1;
    float*       O = blockIdx.z ? g_XR : g_XL;

    const int m0 = blockIdx.y * 128;
    const int n0 = blockIdx.x * 128;

    __shared__ __align__(16) float sA[128][20];
    __shared__ __align__(16) float sW[16][132];

    const int tid = threadIdx.x;
    const int ty = tid >> 4, tx = tid & 15;

    float acc[8][8];
#pragma unroll
    for (int i = 0; i < 8; i++)
#pragma unroll
        for (int j = 0; j < 8; j++) acc[i][j] = 0.f;

    for (int kt = 0; kt < K; kt += 16) {
#pragma unroll
        for (int u = 0; u < 2; u++) {
            int slot = tid + u * 256;
            int row = slot >> 2, ch = slot & 3;
            int gr = m0 + row;
            float4 v = make_float4(0.f, 0.f, 0.f, 0.f);
            if (gr < NN) v = *(const float4*)(A + (size_t)gr * K + kt + ch * 4);
            *(float4*)&sA[row][ch * 4] = v;
        }
#pragma unroll
        for (int u = 0; u < 2; u++) {
            int slot = tid + u * 256;
            int kk = slot >> 5, nc = (slot & 31) * 4;
            float4 v = *(const float4*)(W + (size_t)(kt + kk) * NHC + n0 + nc);
            *(float4*)&sW[kk][nc] = v;
        }
        __syncthreads();

#pragma unroll
        for (int kk = 0; kk < 16; kk++) {
            float a[8];
#pragma unroll
            for (int i = 0; i < 8; i++) a[i] = sA[ty * 8 + i][kk];
            float4 w0 = *(float4*)&sW[kk][tx * 8];
            float4 w1 = *(float4*)&sW[kk][tx * 8 + 4];
            float w[8] = {w0.x, w0.y, w0.z, w0.w, w1.x, w1.y, w1.z, w1.w};
#pragma unroll
            for (int i = 0; i < 8; i++)
#pragma unroll
                for (int j = 0; j < 8; j++)
                    acc[i][j] = fmaf(a[i], w[j], acc[i][j]);
        }
        __syncthreads();
    }

    float4 bv0 = *(const float4*)(b + n0 + tx * 8);
    float4 bv1 = *(const float4*)(b + n0 + tx * 8 + 4);
#pragma unroll
    for (int i = 0; i < 8; i++) {
        int gr = m0 + ty * 8 + i;
        if (gr < NN) {
            float4 o0 = make_float4(acc[i][0] + bv0.x, acc[i][1] + bv0.y,
                                    acc[i][2] + bv0.z, acc[i][3] + bv0.w);
            float4 o1 = make_float4(acc[i][4] + bv1.x, acc[i][5] + bv1.y,
                                    acc[i][6] + bv1.z, acc[i][7] + bv1.w);
            float* op = O + (size_t)gr * NHC + n0 + tx * 8;
            *(float4*)op = o0;
            *(float4*)(op + 4) = o1;
        }
    }
}

// ---------------- pass A: logits -> p = exp(logit), denominator scatter --------
// 64 threads per edge, 4 channels per thread (float4). No shared memory, no
// barriers: edge_attr is read via uniform-address broadcast loads.
__global__ __launch_bounds__(256) void k_logits(
    const float* __restrict__ ea,
    const float* __restrict__ We, const float* __restrict__ att)
{
    const int tid   = threadIdx.x;
    const int e_loc = tid >> 6;           // 0..3
    const int quad  = tid & 63;           // channel quad
    const int ch0   = quad * 4;
    const int head  = quad >> 4;          // 0..3

    float4 we4[9];
#pragma unroll
    for (int k = 0; k < 9; k++) we4[k] = *(const float4*)(We + k * NHC + ch0);
    const float4 att4 = *(const float4*)(att + ch0);

    for (int ebase = blockIdx.x * 4; ebase < NE; ebase += gridDim.x * 4) {
        const int e   = ebase + e_loc;
        const int src = g_SRC[e];
        const int dst = g_DST[e];

        const float4 xl4 = *(const float4*)(g_XL + (size_t)src * NHC + ch0);
        const float4 xr4 = *(const float4*)(g_XR + (size_t)dst * NHC + ch0);

        // edge projection: 9 broadcast loads (uniform address per warp)
        const float* eap = ea + (size_t)e * 9;
        float4 ev = make_float4(0.f, 0.f, 0.f, 0.f);
#pragma unroll
        for (int k = 0; k < 9; k++) {
            const float a = __ldg(eap + k);
            ev.x = fmaf(we4[k].x, a, ev.x);
            ev.y = fmaf(we4[k].y, a, ev.y);
            ev.z = fmaf(we4[k].z, a, ev.z);
            ev.w = fmaf(we4[k].w, a, ev.w);
        }
        float mx = xl4.x + xr4.x + ev.x;
        float my = xl4.y + xr4.y + ev.y;
        float mz = xl4.z + xr4.z + ev.z;
        float mw = xl4.w + xr4.w + ev.w;
        mx = (mx > 0.f) ? mx : 0.2f * mx;   // leaky_relu slope 0.2
        my = (my > 0.f) ? my : 0.2f * my;
        mz = (mz > 0.f) ? mz : 0.2f * mz;
        mw = (mw > 0.f) ? mw : 0.2f * mw;
        float part = att4.x * mx;
        part = fmaf(att4.y, my, part);
        part = fmaf(att4.z, mz, part);
        part = fmaf(att4.w, mw, part);

        // reduce over the 16 lanes of this head
        part += __shfl_down_sync(0xffffffffu, part, 8, 16);
        part += __shfl_down_sync(0xffffffffu, part, 4, 16);
        part += __shfl_down_sync(0xffffffffu, part, 2, 16);
        part += __shfl_down_sync(0xffffffffu, part, 1, 16);

        if ((quad & 15) == 0) {             // reduce root per head
            const float p = __expf(part);
            g_P[(size_t)e * NHEADS + head] = p;
            atomicAdd(&g_DEN[(size_t)dst * NHEADS + head], p);
        }
    }
}

// ---------------- invert denominators (fold 1/H head-mean in) ----------------
__global__ void k_invden() {
    int i = blockIdx.x * 256 + threadIdx.x;
    if (i < NN * NHEADS) g_DEN[i] = __fdividef(0.25f, g_DEN[i] + 1e-16f);
}

// ---------------- pass B: scatter messages (head-mean folded into alpha) -------
// 16 threads per edge, 16 edges per 256-thread block.
__global__ __launch_bounds__(256) void k_edge_b() {
    const int tid = threadIdx.x;
    const int slot = tid >> 4, q = tid & 15;
    const int e = blockIdx.x * 16 + slot;
    const int src = g_SRC[e];
    const int dst = g_DST[e];

    float al[4];
#pragma unroll
    for (int h = 0; h < 4; h++)
        al[h] = g_P[(size_t)e * 4 + h] * g_DEN[(size_t)dst * 4 + h];

    float4 acc = make_float4(0.f, 0.f, 0.f, 0.f);
    const float* base = g_XL + (size_t)src * NHC + q * 4;
#pragma unroll
    for (int h = 0; h < 4; h++) {
        float4 v = *(const float4*)(base + h * 64);
        acc.x = fmaf(v.x, al[h], acc.x);
        acc.y = fmaf(v.y, al[h], acc.y);
        acc.z = fmaf(v.z, al[h], acc.z);
        acc.w = fmaf(v.w, al[h], acc.w);
    }
    atomicAdd((float4*)(g_ACC + (size_t)dst * 64 + q * 4), acc);
}

// ---------------- node update: bias, gating, leaky-relu ----------------
__global__ void k_node(const float* __restrict__ bias, const float* __restrict__ gates,
                       int layer, float* __restrict__ out) {
    int i = blockIdx.x * 256 + threadIdx.x;   // grid covers exactly NN*NHID
    int c = i & 63;
    float val = g_ACC[i] + bias[c];
    if (layer == 0) {
        g_A[i] = (val > 0.f) ? val : 0.01f * val;
    } else {
        float g = 1.f / (1.f + __expf(-gates[layer - 1]));
        float h = g * val + (1.f - g) * g_A[i];
        if (layer == 1) g_A[i] = (h > 0.f) ? h : 0.01f * h;
        else            out[i] = h;
    }
}

// ---------------- host ----------------
extern "C" void kernel_launch(void* const* d_in, const int* in_sizes, int n_in,
                              void* d_out, int out_size) {
    (void)out_size;
    const float *x = 0, *edge_attr = 0, *gates = 0;
    const float *W32k[4] = {0, 0, 0, 0};  int n32k = 0;   // init_Wl, init_Wr, Wl, Wr
    const float *a256[3] = {0, 0, 0};     int n256 = 0;   // init_bl, init_br, init_att
    const float *a512[3] = {0, 0, 0};     int n512 = 0;   // bl, br, att
    const float *init_We = 0, *WeL = 0, *init_bias = 0, *biasL = 0;
    const void* ei = 0;

    for (int i = 0; i < n_in; i++) {
        const void* p = d_in[i];
        switch (in_sizes[i]) {
            case 6400000: x = (const float*)p; break;
            case 7200000: edge_attr = (const float*)p; break;
            case 1600000: ei = p; break;
            case 3:       gates = (const float*)p; break;
            case 32768:   if (n32k < 4) W32k[n32k++] = (const float*)p; break;
            case 256:     if (n256 < 3) a256[n256++] = (const float*)p; break;
            case 512:     if (n512 < 3) a512[n512++] = (const float*)p; break;
            case 2304:    init_We = (const float*)p; break;
            case 4608:    WeL = (const float*)p; break;
            case 64:      init_bias = (const float*)p; break;
            case 128:     biasL = (const float*)p; break;
            default: break;
        }
    }
    const float *Wl0 = W32k[0], *Wr0 = W32k[1], *WlL = W32k[2], *WrL = W32k[3];
    const float *bl0 = a256[0], *br0 = a256[1], *att0 = a256[2];
    const float *blL = a512[0], *brL = a512[1], *attL = a512[2];
    float* out = (float*)d_out;

    k_convert<<<NE / 256, 256>>>(ei);

    const dim3 gemm_grid(2, (NN + 127) / 128, 2);

    for (int l = 0; l < 3; l++) {
        k_zero<<<NN * NHID / 256, 256>>>();

        if (l == 0) {
            k_gemm<128><<<gemm_grid, 256>>>(x, 0, Wl0, bl0, Wr0, br0);
        } else {
            const float* Wl = WlL + (size_t)(l - 1) * 64 * 256;
            const float* Wr = WrL + (size_t)(l - 1) * 64 * 256;
            const float* bl = blL + (size_t)(l - 1) * 256;
            const float* br = brL + (size_t)(l - 1) * 256;
            k_gemm<64><<<gemm_grid, 256>>>(0, 1, Wl, bl, Wr, br);
        }

        const float* We  = l ? (WeL  + (size_t)(l - 1) * 9 * 256) : init_We;
        const float* att = l ? (attL + (size_t)(l - 1) * 256)     : att0;

        k_logits<<<2368, 256>>>(edge_attr, We, att);
        k_invden<<<(NN * NHEADS + 255) / 256, 256>>>();
        k_edge_b<<<NE / 16, 256>>>();

        const float* bias = l ? (biasL + (size_t)(l - 1) * 64) : init_bias;
        k_node<<<NN * NHID / 256, 256>>>(bias, gates, l, out);
    }
}

// round 8
// speedup vs baseline: 1.3242x; 1.1106x over previous
#include <cuda_runtime.h>
#include <math.h>

#define NN      50000
#define NE      800000
#define NHEADS  4
#define NHID    64
#define NHC     256

// ---------------- scratch (static device globals; no allocation) ----------------
__device__ __align__(16) float g_XL [(size_t)NN * NHC];    // 51.2 MB
__device__ __align__(16) float g_XR [(size_t)NN * NHC];    // 51.2 MB
__device__ __align__(16) float g_P  [(size_t)NE * NHEADS]; // 12.8 MB exp(logit)
__device__ __align__(16) float g_DEN[(size_t)NN * NHEADS]; // 0.8 MB  denom -> 0.25/(d+eps)
__device__ __align__(16) float g_ACC[(size_t)NN * NHID];   // 12.8 MB head-mean messages
__device__ __align__(16) float g_A  [(size_t)NN * NHID];   // 12.8 MB layer input
__device__ __align__(16) int   g_SRC[NE];
__device__ __align__(16) int   g_DST[NE];

// ---------------- canonicalize edge_index (handles int32 OR int64 input) -------
__global__ void k_convert(const void* __restrict__ ei_raw) {
    __shared__ int s_is64;
    const int* ei32 = (const int*)ei_raw;
    if (threadIdx.x == 0) {
        int nz = 0;
#pragma unroll
        for (int i = 0; i < 32; i++) nz |= ei32[2 * i + 1];
        s_is64 = (nz == 0);
    }
    __syncthreads();
    int e = blockIdx.x * 256 + threadIdx.x;   // grid covers exactly NE
    if (s_is64) {
        const long long* ei64 = (const long long*)ei_raw;
        g_SRC[e] = (int)ei64[e];
        g_DST[e] = (int)ei64[NE + e];
    } else {
        g_SRC[e] = ei32[e];
        g_DST[e] = ei32[NE + e];
    }
}

// ---------------- zero accumulators + denominators ----------------
__global__ void k_zero() {
    int i = blockIdx.x * 256 + threadIdx.x;   // grid covers exactly NN*NHID
    g_ACC[i] = 0.f;
    if (i < NN * NHEADS) g_DEN[i] = 0.f;
}

// ---------------- dual GEMM: O = A[M,K] @ W[K,256] + b ----------------
template <int K>
__global__ __launch_bounds__(256) void k_gemm(
    const float* __restrict__ Aext, int useA,
    const float* __restrict__ W1, const float* __restrict__ b1,
    const float* __restrict__ W2, const float* __restrict__ b2)
{
    const float* A = useA ? g_A : Aext;
    const float* W = blockIdx.z ? W2 : W1;
    const float* b = blockIdx.z ? b2 : b1;
    float*       O = blockIdx.z ? g_XR : g_XL;

    const int m0 = blockIdx.y * 128;
    const int n0 = blockIdx.x * 128;

    __shared__ __align__(16) float sA[128][20];
    __shared__ __align__(16) float sW[16][132];

    const int tid = threadIdx.x;
    const int ty = tid >> 4, tx = tid & 15;

    float acc[8][8];
#pragma unroll
    for (int i = 0; i < 8; i++)
#pragma unroll
        for (int j = 0; j < 8; j++) acc[i][j] = 0.f;

    for (int kt = 0; kt < K; kt += 16) {
#pragma unroll
        for (int u = 0; u < 2; u++) {
            int slot = tid + u * 256;
            int row = slot >> 2, ch = slot & 3;
            int gr = m0 + row;
            float4 v = make_float4(0.f, 0.f, 0.f, 0.f);
            if (gr < NN) v = *(const float4*)(A + (size_t)gr * K + kt + ch * 4);
            *(float4*)&sA[row][ch * 4] = v;
        }
#pragma unroll
        for (int u = 0; u < 2; u++) {
            int slot = tid + u * 256;
            int kk = slot >> 5, nc = (slot & 31) * 4;
            float4 v = *(const float4*)(W + (size_t)(kt + kk) * NHC + n0 + nc);
            *(float4*)&sW[kk][nc] = v;
        }
        __syncthreads();

#pragma unroll
        for (int kk = 0; kk < 16; kk++) {
            float a[8];
#pragma unroll
            for (int i = 0; i < 8; i++) a[i] = sA[ty * 8 + i][kk];
            float4 w0 = *(float4*)&sW[kk][tx * 8];
            float4 w1 = *(float4*)&sW[kk][tx * 8 + 4];
            float w[8] = {w0.x, w0.y, w0.z, w0.w, w1.x, w1.y, w1.z, w1.w};
#pragma unroll
            for (int i = 0; i < 8; i++)
#pragma unroll
                for (int j = 0; j < 8; j++)
                    acc[i][j] = fmaf(a[i], w[j], acc[i][j]);
        }
        __syncthreads();
    }

    float4 bv0 = *(const float4*)(b + n0 + tx * 8);
    float4 bv1 = *(const float4*)(b + n0 + tx * 8 + 4);
#pragma unroll
    for (int i = 0; i < 8; i++) {
        int gr = m0 + ty * 8 + i;
        if (gr < NN) {
            float4 o0 = make_float4(acc[i][0] + bv0.x, acc[i][1] + bv0.y,
                                    acc[i][2] + bv0.z, acc[i][3] + bv0.w);
            float4 o1 = make_float4(acc[i][4] + bv1.x, acc[i][5] + bv1.y,
                                    acc[i][6] + bv1.z, acc[i][7] + bv1.w);
            float* op = O + (size_t)gr * NHC + n0 + tx * 8;
            *(float4*)op = o0;
            *(float4*)(op + 4) = o1;
        }
    }
}

// ---------------- pass A: logits -> p = exp(logit), denominator scatter --------
// 64 threads per edge, 4 channels per thread (float4), 128-thread blocks
// (2 edges per block iteration). 2-stage software pipeline: next iteration's
// index + xl/xr gathers issue before the current edge's compute.
__global__ __launch_bounds__(128, 6) void k_logits(
    const float* __restrict__ ea,
    const float* __restrict__ We, const float* __restrict__ att)
{
    const int tid   = threadIdx.x;
    const int e_loc = tid >> 6;           // 0..1
    const int quad  = tid & 63;           // channel quad
    const int ch0   = quad * 4;
    const int head  = quad >> 4;          // 0..3

    float4 we4[9];
#pragma unroll
    for (int k = 0; k < 9; k++) we4[k] = *(const float4*)(We + k * NHC + ch0);
    const float4 att4 = *(const float4*)(att + ch0);

    const int stride = gridDim.x * 2;
    int e = blockIdx.x * 2 + e_loc;

    // pipeline prologue: load stage for the first edge
    int   dst = g_DST[e];
    float4 xl4 = *(const float4*)(g_XL + (size_t)g_SRC[e] * NHC + ch0);
    float4 xr4 = *(const float4*)(g_XR + (size_t)dst * NHC + ch0);

    while (e < NE) {
        // ---- prefetch next stage (clamped; values unused past the end) ----
        const int e_next = e + stride;
        const int en = (e_next < NE) ? e_next : (NE - 1);
        const int src_n = __ldg(&g_SRC[en]);
        const int dst_n = __ldg(&g_DST[en]);
        const float4 xl_n = *(const float4*)(g_XL + (size_t)src_n * NHC + ch0);
        const float4 xr_n = *(const float4*)(g_XR + (size_t)dst_n * NHC + ch0);

        // ---- current edge: projection (9 broadcast loads, uniform per warp) ----
        const float* eap = ea + (size_t)e * 9;
        float4 ev = make_float4(0.f, 0.f, 0.f, 0.f);
#pragma unroll
        for (int k = 0; k < 9; k++) {
            const float a = __ldg(eap + k);
            ev.x = fmaf(we4[k].x, a, ev.x);
            ev.y = fmaf(we4[k].y, a, ev.y);
            ev.z = fmaf(we4[k].z, a, ev.z);
            ev.w = fmaf(we4[k].w, a, ev.w);
        }
        float mx = xl4.x + xr4.x + ev.x;
        float my = xl4.y + xr4.y + ev.y;
        float mz = xl4.z + xr4.z + ev.z;
        float mw = xl4.w + xr4.w + ev.w;
        mx = (mx > 0.f) ? mx : 0.2f * mx;   // leaky_relu slope 0.2
        my = (my > 0.f) ? my : 0.2f * my;
        mz = (mz > 0.f) ? mz : 0.2f * mz;
        mw = (mw > 0.f) ? mw : 0.2f * mw;
        float part = att4.x * mx;
        part = fmaf(att4.y, my, part);
        part = fmaf(att4.z, mz, part);
        part = fmaf(att4.w, mw, part);

        // reduce over the 16 lanes of this head
        part += __shfl_down_sync(0xffffffffu, part, 8, 16);
        part += __shfl_down_sync(0xffffffffu, part, 4, 16);
        part += __shfl_down_sync(0xffffffffu, part, 2, 16);
        part += __shfl_down_sync(0xffffffffu, part, 1, 16);

        if ((quad & 15) == 0) {             // reduce root per head
            const float p = __expf(part);
            g_P[(size_t)e * NHEADS + head] = p;
            atomicAdd(&g_DEN[(size_t)dst * NHEADS + head], p);
        }

        // ---- rotate pipeline ----
        e = e_next;
        dst = dst_n;
        xl4 = xl_n;
        xr4 = xr_n;
    }
}

// ---------------- invert denominators (fold 1/H head-mean in) ----------------
__global__ void k_invden() {
    int i = blockIdx.x * 256 + threadIdx.x;
    if (i < NN * NHEADS) g_DEN[i] = __fdividef(0.25f, g_DEN[i] + 1e-16f);
}

// ---------------- pass B: scatter messages (head-mean folded into alpha) -------
// 16 threads per edge, 16 edges per 256-thread block.
__global__ __launch_bounds__(256) void k_edge_b() {
    const int tid = threadIdx.x;
    const int slot = tid >> 4, q = tid & 15;
    const int e = blockIdx.x * 16 + slot;
    const int src = g_SRC[e];
    const int dst = g_DST[e];

    float al[4];
#pragma unroll
    for (int h = 0; h < 4; h++)
        al[h] = g_P[(size_t)e * 4 + h] * g_DEN[(size_t)dst * 4 + h];

    float4 acc = make_float4(0.f, 0.f, 0.f, 0.f);
    const float* base = g_XL + (size_t)src * NHC + q * 4;
#pragma unroll
    for (int h = 0; h < 4; h++) {
        float4 v = *(const float4*)(base + h * 64);
        acc.x = fmaf(v.x, al[h], acc.x);
        acc.y = fmaf(v.y, al[h], acc.y);
        acc.z = fmaf(v.z, al[h], acc.z);
        acc.w = fmaf(v.w, al[h], acc.w);
    }
    atomicAdd((float4*)(g_ACC + (size_t)dst * 64 + q * 4), acc);
}

// ---------------- node update: bias, gating, leaky-relu ----------------
__global__ void k_node(const float* __restrict__ bias, const float* __restrict__ gates,
                       int layer, float* __restrict__ out) {
    int i = blockIdx.x * 256 + threadIdx.x;   // grid covers exactly NN*NHID
    int c = i & 63;
    float val = g_ACC[i] + bias[c];
    if (layer == 0) {
        g_A[i] = (val > 0.f) ? val : 0.01f * val;
    } else {
        float g = 1.f / (1.f + __expf(-gates[layer - 1]));
        float h = g * val + (1.f - g) * g_A[i];
        if (layer == 1) g_A[i] = (h > 0.f) ? h : 0.01f * h;
        else            out[i] = h;
    }
}

// ---------------- host ----------------
extern "C" void kernel_launch(void* const* d_in, const int* in_sizes, int n_in,
                              void* d_out, int out_size) {
    (void)out_size;
    const float *x = 0, *edge_attr = 0, *gates = 0;
    const float *W32k[4] = {0, 0, 0, 0};  int n32k = 0;   // init_Wl, init_Wr, Wl, Wr
    const float *a256[3] = {0, 0, 0};     int n256 = 0;   // init_bl, init_br, init_att
    const float *a512[3] = {0, 0, 0};     int n512 = 0;   // bl, br, att
    const float *init_We = 0, *WeL = 0, *init_bias = 0, *biasL = 0;
    const void* ei = 0;

    for (int i = 0; i < n_in; i++) {
        const void* p = d_in[i];
        switch (in_sizes[i]) {
            case 6400000: x = (const float*)p; break;
            case 7200000: edge_attr = (const float*)p; break;
            case 1600000: ei = p; break;
            case 3:       gates = (const float*)p; break;
            case 32768:   if (n32k < 4) W32k[n32k++] = (const float*)p; break;
            case 256:     if (n256 < 3) a256[n256++] = (const float*)p; break;
            case 512:     if (n512 < 3) a512[n512++] = (const float*)p; break;
            case 2304:    init_We = (const float*)p; break;
            case 4608:    WeL = (const float*)p; break;
            case 64:      init_bias = (const float*)p; break;
            case 128:     biasL = (const float*)p; break;
            default: break;
        }
    }
    const float *Wl0 = W32k[0], *Wr0 = W32k[1], *WlL = W32k[2], *WrL = W32k[3];
    const float *bl0 = a256[0], *br0 = a256[1], *att0 = a256[2];
    const float *blL = a512[0], *brL = a512[1], *attL = a512[2];
    float* out = (float*)d_out;

    k_convert<<<NE / 256, 256>>>(ei);

    const dim3 gemm_grid(2, (NN + 127) / 128, 2);

    for (int l = 0; l < 3; l++) {
        k_zero<<<NN * NHID / 256, 256>>>();

        if (l == 0) {
            k_gemm<128><<<gemm_grid, 256>>>(x, 0, Wl0, bl0, Wr0, br0);
        } else {
            const float* Wl = WlL + (size_t)(l - 1) * 64 * 256;
            const float* Wr = WrL + (size_t)(l - 1) * 64 * 256;
            const float* bl = blL + (size_t)(l - 1) * 256;
            const float* br = brL + (size_t)(l - 1) * 256;
            k_gemm<64><<<gemm_grid, 256>>>(0, 1, Wl, bl, Wr, br);
        }

        const float* We  = l ? (WeL  + (size_t)(l - 1) * 9 * 256) : init_We;
        const float* att = l ? (attL + (size_t)(l - 1) * 256)     : att0;

        k_logits<<<2368, 128>>>(edge_attr, We, att);
        k_invden<<<(NN * NHEADS + 255) / 256, 256>>>();
        k_edge_b<<<NE / 16, 256>>>();

        const float* bias = l ? (biasL + (size_t)(l - 1) * 64) : init_bias;
        k_node<<<NN * NHID / 256, 256>>>(bias, gates, l, out);
    }
}

// round 9
// speedup vs baseline: 1.3585x; 1.0258x over previous
#include <cuda_runtime.h>
#include <math.h>

#define NN      50000
#define NE      800000
#define NHEADS  4
#define NHID    64
#define NHC     256

typedef unsigned long long ull;

// ---- packed f32x2 helpers (PTX ISA 8.6, sm_100+) ----
__device__ __forceinline__ ull pk2(float lo, float hi) {
    ull r; asm("mov.b64 %0, {%1, %2};" : "=l"(r) : "f"(lo), "f"(hi)); return r;
}
__device__ __forceinline__ void upk2(float& lo, float& hi, ull v) {
    asm("mov.b64 {%0, %1}, %2;" : "=f"(lo), "=f"(hi) : "l"(v));
}
__device__ __forceinline__ ull ffma2(ull a, ull b, ull c) {
    ull d; asm("fma.rn.f32x2 %0, %1, %2, %3;" : "=l"(d) : "l"(a), "l"(b), "l"(c)); return d;
}
__device__ __forceinline__ ull fadd2(ull a, ull b) {
    ull d; asm("add.rn.f32x2 %0, %1, %2;" : "=l"(d) : "l"(a), "l"(b)); return d;
}

// ---------------- scratch (static device globals; no allocation) ----------------
__device__ __align__(16) float g_XL [(size_t)NN * NHC];    // 51.2 MB
__device__ __align__(16) float g_XR [(size_t)NN * NHC];    // 51.2 MB
__device__ __align__(16) float g_P  [(size_t)NE * NHEADS]; // 12.8 MB exp(logit)
__device__ __align__(16) float g_DEN[(size_t)NN * NHEADS]; // 0.8 MB
__device__ __align__(16) float g_ACC[(size_t)NN * NHID];   // 12.8 MB
__device__ __align__(16) float g_A  [(size_t)NN * NHID];   // 12.8 MB
__device__ __align__(16) int   g_SRC[NE];
__device__ __align__(16) int   g_DST[NE];

// ---------------- canonicalize edge_index (handles int32 OR int64 input) -------
__global__ void k_convert(const void* __restrict__ ei_raw) {
    __shared__ int s_is64;
    const int* ei32 = (const int*)ei_raw;
    if (threadIdx.x == 0) {
        int nz = 0;
#pragma unroll
        for (int i = 0; i < 32; i++) nz |= ei32[2 * i + 1];
        s_is64 = (nz == 0);
    }
    __syncthreads();
    int e = blockIdx.x * 256 + threadIdx.x;   // grid covers exactly NE
    if (s_is64) {
        const long long* ei64 = (const long long*)ei_raw;
        g_SRC[e] = (int)ei64[e];
        g_DST[e] = (int)ei64[NE + e];
    } else {
        g_SRC[e] = ei32[e];
        g_DST[e] = ei32[NE + e];
    }
}

// ---------------- zero accumulators + denominators ----------------
__global__ void k_zero() {
    int i = blockIdx.x * 256 + threadIdx.x;   // grid covers exactly NN*NHID
    g_ACC[i] = 0.f;
    if (i < NN * NHEADS) g_DEN[i] = 0.f;
}

// ---------------- dual GEMM: O = A[M,K] @ W[K,256] + b  (packed FFMA2) --------
template <int K>
__global__ __launch_bounds__(256) void k_gemm(
    const float* __restrict__ Aext, int useA,
    const float* __restrict__ W1, const float* __restrict__ b1,
    const float* __restrict__ W2, const float* __restrict__ b2)
{
    const float* A = useA ? g_A : Aext;
    const float* W = blockIdx.z ? W2 : W1;
    const float* b = blockIdx.z ? b2 : b1;
    float*       O = blockIdx.z ? g_XR : g_XL;

    const int m0 = blockIdx.y * 128;
    const int n0 = blockIdx.x * 128;

    __shared__ __align__(16) float sA[128][20];
    __shared__ __align__(16) float sW[16][132];

    const int tid = threadIdx.x;
    const int ty = tid >> 4, tx = tid & 15;

    ull acc2[8][4];   // pairs along N: (j, j+1)
#pragma unroll
    for (int i = 0; i < 8; i++)
#pragma unroll
        for (int p = 0; p < 4; p++) acc2[i][p] = 0ull;   // (0.f, 0.f)

    for (int kt = 0; kt < K; kt += 16) {
#pragma unroll
        for (int u = 0; u < 2; u++) {
            int slot = tid + u * 256;
            int row = slot >> 2, ch = slot & 3;
            int gr = m0 + row;
            float4 v = make_float4(0.f, 0.f, 0.f, 0.f);
            if (gr < NN) v = *(const float4*)(A + (size_t)gr * K + kt + ch * 4);
            *(float4*)&sA[row][ch * 4] = v;
        }
#pragma unroll
        for (int u = 0; u < 2; u++) {
            int slot = tid + u * 256;
            int kk = slot >> 5, nc = (slot & 31) * 4;
            float4 v = *(const float4*)(W + (size_t)(kt + kk) * NHC + n0 + nc);
            *(float4*)&sW[kk][nc] = v;
        }
        __syncthreads();

#pragma unroll
        for (int kk = 0; kk < 16; kk++) {
            float4 w0 = *(float4*)&sW[kk][tx * 8];
            float4 w1 = *(float4*)&sW[kk][tx * 8 + 4];
            ull w2[4] = { pk2(w0.x, w0.y), pk2(w0.z, w0.w),
                          pk2(w1.x, w1.y), pk2(w1.z, w1.w) };
#pragma unroll
            for (int i = 0; i < 8; i++) {
                const float av = sA[ty * 8 + i][kk];
                const ull a2 = pk2(av, av);
#pragma unroll
                for (int p = 0; p < 4; p++)
                    acc2[i][p] = ffma2(a2, w2[p], acc2[i][p]);
            }
        }
        __syncthreads();
    }

    float4 bv0 = *(const float4*)(b + n0 + tx * 8);
    float4 bv1 = *(const float4*)(b + n0 + tx * 8 + 4);
#pragma unroll
    for (int i = 0; i < 8; i++) {
        int gr = m0 + ty * 8 + i;
        if (gr < NN) {
            float a0, a1, a2v, a3, a4, a5, a6, a7;
            upk2(a0, a1, acc2[i][0]);
            upk2(a2v, a3, acc2[i][1]);
            upk2(a4, a5, acc2[i][2]);
            upk2(a6, a7, acc2[i][3]);
            float4 o0 = make_float4(a0 + bv0.x, a1 + bv0.y, a2v + bv0.z, a3 + bv0.w);
            float4 o1 = make_float4(a4 + bv1.x, a5 + bv1.y, a6 + bv1.z, a7 + bv1.w);
            float* op = O + (size_t)gr * NHC + n0 + tx * 8;
            *(float4*)op = o0;
            *(float4*)(op + 4) = o1;
        }
    }
}

// ---------------- pass A: logits -> p = exp(logit), denominator scatter --------
// 64 threads/edge, 4 channels/thread, 2-stage software pipeline, packed FFMA2
// edge projection.
__global__ __launch_bounds__(128, 6) void k_logits(
    const float* __restrict__ ea,
    const float* __restrict__ We, const float* __restrict__ att)
{
    const int tid   = threadIdx.x;
    const int e_loc = tid >> 6;           // 0..1
    const int quad  = tid & 63;           // channel quad
    const int ch0   = quad * 4;
    const int head  = quad >> 4;          // 0..3

    ull wepk[9][2];
#pragma unroll
    for (int k = 0; k < 9; k++) {
        float4 w = *(const float4*)(We + k * NHC + ch0);
        wepk[k][0] = pk2(w.x, w.y);
        wepk[k][1] = pk2(w.z, w.w);
    }
    const float4 att4 = *(const float4*)(att + ch0);

    const int stride = gridDim.x * 2;
    int e = blockIdx.x * 2 + e_loc;

    // pipeline prologue
    int   dst = g_DST[e];
    float4 xl4 = *(const float4*)(g_XL + (size_t)g_SRC[e] * NHC + ch0);
    float4 xr4 = *(const float4*)(g_XR + (size_t)dst * NHC + ch0);

    while (e < NE) {
        // ---- prefetch next stage ----
        const int e_next = e + stride;
        const int en = (e_next < NE) ? e_next : (NE - 1);
        const int src_n = __ldg(&g_SRC[en]);
        const int dst_n = __ldg(&g_DST[en]);
        const float4 xl_n = *(const float4*)(g_XL + (size_t)src_n * NHC + ch0);
        const float4 xr_n = *(const float4*)(g_XR + (size_t)dst_n * NHC + ch0);

        // ---- projection seeded with xl+xr, packed pairs ----
        ull ev01 = fadd2(pk2(xl4.x, xl4.y), pk2(xr4.x, xr4.y));
        ull ev23 = fadd2(pk2(xl4.z, xl4.w), pk2(xr4.z, xr4.w));
        const float* eap = ea + (size_t)e * 9;
#pragma unroll
        for (int k = 0; k < 9; k++) {
            const float a = __ldg(eap + k);
            const ull a2 = pk2(a, a);
            ev01 = ffma2(a2, wepk[k][0], ev01);
            ev23 = ffma2(a2, wepk[k][1], ev23);
        }
        float mx, my, mz, mw;
        upk2(mx, my, ev01);
        upk2(mz, mw, ev23);
        mx = (mx > 0.f) ? mx : 0.2f * mx;   // leaky_relu slope 0.2
        my = (my > 0.f) ? my : 0.2f * my;
        mz = (mz > 0.f) ? mz : 0.2f * mz;
        mw = (mw > 0.f) ? mw : 0.2f * mw;
        float part = att4.x * mx;
        part = fmaf(att4.y, my, part);
        part = fmaf(att4.z, mz, part);
        part = fmaf(att4.w, mw, part);

        // reduce over the 16 lanes of this head
        part += __shfl_down_sync(0xffffffffu, part, 8, 16);
        part += __shfl_down_sync(0xffffffffu, part, 4, 16);
        part += __shfl_down_sync(0xffffffffu, part, 2, 16);
        part += __shfl_down_sync(0xffffffffu, part, 1, 16);

        if ((quad & 15) == 0) {             // reduce root per head
            const float p = __expf(part);
            g_P[(size_t)e * NHEADS + head] = p;
            atomicAdd(&g_DEN[(size_t)dst * NHEADS + head], p);
        }

        // ---- rotate pipeline ----
        e = e_next;
        dst = dst_n;
        xl4 = xl_n;
        xr4 = xr_n;
    }
}

// ---------------- invert denominators (fold 1/H head-mean in) ----------------
__global__ void k_invden() {
    int i = blockIdx.x * 256 + threadIdx.x;
    if (i < NN * NHEADS) g_DEN[i] = __fdividef(0.25f, g_DEN[i] + 1e-16f);
}

// ---------------- pass B: scatter messages (head-mean folded into alpha) -------
__global__ __launch_bounds__(256) void k_edge_b() {
    const int tid = threadIdx.x;
    const int slot = tid >> 4, q = tid & 15;
    const int e = blockIdx.x * 16 + slot;
    const int src = g_SRC[e];
    const int dst = g_DST[e];

    float al[4];
#pragma unroll
    for (int h = 0; h < 4; h++)
        al[h] = g_P[(size_t)e * 4 + h] * g_DEN[(size_t)dst * 4 + h];

    float4 acc = make_float4(0.f, 0.f, 0.f, 0.f);
    const float* base = g_XL + (size_t)src * NHC + q * 4;
#pragma unroll
    for (int h = 0; h < 4; h++) {
        float4 v = *(const float4*)(base + h * 64);
        acc.x = fmaf(v.x, al[h], acc.x);
        acc.y = fmaf(v.y, al[h], acc.y);
        acc.z = fmaf(v.z, al[h], acc.z);
        acc.w = fmaf(v.w, al[h], acc.w);
    }
    atomicAdd((float4*)(g_ACC + (size_t)dst * 64 + q * 4), acc);
}

// ---------------- node update: bias, gating, leaky-relu ----------------
__global__ void k_node(const float* __restrict__ bias, const float* __restrict__ gates,
                       int layer, float* __restrict__ out) {
    int i = blockIdx.x * 256 + threadIdx.x;   // grid covers exactly NN*NHID
    int c = i & 63;
    float val = g_ACC[i] + bias[c];
    if (layer == 0) {
        g_A[i] = (val > 0.f) ? val : 0.01f * val;
    } else {
        float g = 1.f / (1.f + __expf(-gates[layer - 1]));
        float h = g * val + (1.f - g) * g_A[i];
        if (layer == 1) g_A[i] = (h > 0.f) ? h : 0.01f * h;
        else            out[i] = h;
    }
}

// ---------------- host ----------------
extern "C" void kernel_launch(void* const* d_in, const int* in_sizes, int n_in,
                              void* d_out, int out_size) {
    (void)out_size;
    const float *x = 0, *edge_attr = 0, *gates = 0;
    const float *W32k[4] = {0, 0, 0, 0};  int n32k = 0;   // init_Wl, init_Wr, Wl, Wr
    const float *a256[3] = {0, 0, 0};     int n256 = 0;   // init_bl, init_br, init_att
    const float *a512[3] = {0, 0, 0};     int n512 = 0;   // bl, br, att
    const float *init_We = 0, *WeL = 0, *init_bias = 0, *biasL = 0;
    const void* ei = 0;

    for (int i = 0; i < n_in; i++) {
        const void* p = d_in[i];
        switch (in_sizes[i]) {
            case 6400000: x = (const float*)p; break;
            case 7200000: edge_attr = (const float*)p; break;
            case 1600000: ei = p; break;
            case 3:       gates = (const float*)p; break;
            case 32768:   if (n32k < 4) W32k[n32k++] = (const float*)p; break;
            case 256:     if (n256 < 3) a256[n256++] = (const float*)p; break;
            case 512:     if (n512 < 3) a512[n512++] = (const float*)p; break;
            case 2304:    init_We = (const float*)p; break;
            case 4608:    WeL = (const float*)p; break;
            case 64:      init_bias = (const float*)p; break;
            case 128:     biasL = (const float*)p; break;
            default: break;
        }
    }
    const float *Wl0 = W32k[0], *Wr0 = W32k[1], *WlL = W32k[2], *WrL = W32k[3];
    const float *bl0 = a256[0], *br0 = a256[1], *att0 = a256[2];
    const float *blL = a512[0], *brL = a512[1], *attL = a512[2];
    float* out = (float*)d_out;

    k_convert<<<NE / 256, 256>>>(ei);

    const dim3 gemm_grid(2, (NN + 127) / 128, 2);

    for (int l = 0; l < 3; l++) {
        k_zero<<<NN * NHID / 256, 256>>>();

        if (l == 0) {
            k_gemm<128><<<gemm_grid, 256>>>(x, 0, Wl0, bl0, Wr0, br0);
        } else {
            const float* Wl = WlL + (size_t)(l - 1) * 64 * 256;
            const float* Wr = WrL + (size_t)(l - 1) * 64 * 256;
            const float* bl = blL + (size_t)(l - 1) * 256;
            const float* br = brL + (size_t)(l - 1) * 256;
            k_gemm<64><<<gemm_grid, 256>>>(0, 1, Wl, bl, Wr, br);
        }

        const float* We  = l ? (WeL  + (size_t)(l - 1) * 9 * 256) : init_We;
        const float* att = l ? (attL + (size_t)(l - 1) * 256)     : att0;

        k_logits<<<2368, 128>>>(edge_attr, We, att);
        k_invden<<<(NN * NHEADS + 255) / 256, 256>>>();
        k_edge_b<<<NE / 16, 256>>>();

        const float* bias = l ? (biasL + (size_t)(l - 1) * 64) : init_bias;
        k_node<<<NN * NHID / 256, 256>>>(bias, gates, l, out);
    }
}

// round 10
// speedup vs baseline: 1.6120x; 1.1866x over previous
#include <cuda_runtime.h>
#include <math.h>

#define NN      50000
#define NE      800000
#define NHEADS  4
#define NHID    64
#define NHC     256

typedef unsigned long long ull;

// ---- packed f32x2 helpers (PTX ISA 8.6, sm_100+) ----
__device__ __forceinline__ ull pk2(float lo, float hi) {
    ull r; asm("mov.b64 %0, {%1, %2};" : "=l"(r) : "f"(lo), "f"(hi)); return r;
}
__device__ __forceinline__ void upk2(float& lo, float& hi, ull v) {
    asm("mov.b64 {%0, %1}, %2;" : "=f"(lo), "=f"(hi) : "l"(v));
}
__device__ __forceinline__ ull ffma2(ull a, ull b, ull c) {
    ull d; asm("fma.rn.f32x2 %0, %1, %2, %3;" : "=l"(d) : "l"(a), "l"(b), "l"(c)); return d;
}
__device__ __forceinline__ ull fadd2(ull a, ull b) {
    ull d; asm("add.rn.f32x2 %0, %1, %2;" : "=l"(d) : "l"(a), "l"(b)); return d;
}

// ---------------- scratch (static device globals; no allocation) ----------------
// NOTE: zero-initialized at module load; k_node re-zeroes g_ACC/g_DEN at the end
// of every layer so each kernel_launch leaves them zeroed for the next call.
__device__ __align__(16) float g_XL [(size_t)NN * NHC];    // 51.2 MB
__device__ __align__(16) float g_XR [(size_t)NN * NHC];    // 51.2 MB
__device__ __align__(16) float g_P  [(size_t)NE * NHEADS]; // 12.8 MB exp(logit)
__device__ __align__(16) float g_DEN[(size_t)NN * NHEADS]; // 0.8 MB
__device__ __align__(16) float g_ACC[(size_t)NN * NHID];   // 12.8 MB
__device__ __align__(16) float g_A  [(size_t)NN * NHID];   // 12.8 MB
__device__ __align__(16) int   g_SRC[NE];
__device__ __align__(16) int   g_DST[NE];

// ---------------- canonicalize edge_index (handles int32 OR int64 input) -------
__global__ void k_convert(const void* __restrict__ ei_raw) {
    __shared__ int s_is64;
    const int* ei32 = (const int*)ei_raw;
    if (threadIdx.x == 0) {
        int nz = 0;
#pragma unroll
        for (int i = 0; i < 32; i++) nz |= ei32[2 * i + 1];
        s_is64 = (nz == 0);
    }
    __syncthreads();
    int e = blockIdx.x * 256 + threadIdx.x;   // grid covers exactly NE
    if (s_is64) {
        const long long* ei64 = (const long long*)ei_raw;
        g_SRC[e] = (int)ei64[e];
        g_DST[e] = (int)ei64[NE + e];
    } else {
        g_SRC[e] = ei32[e];
        g_DST[e] = ei32[NE + e];
    }
}

// ---------------- dual GEMM: O = A[M,K] @ W[K,256] + b  (packed FFMA2) --------
template <int K>
__global__ __launch_bounds__(256) void k_gemm(
    const float* __restrict__ Aext, int useA,
    const float* __restrict__ W1, const float* __restrict__ b1,
    const float* __restrict__ W2, const float* __restrict__ b2)
{
    const float* A = useA ? g_A : Aext;
    const float* W = blockIdx.z ? W2 : W1;
    const float* b = blockIdx.z ? b2 : b1;
    float*       O = blockIdx.z ? g_XR : g_XL;

    const int m0 = blockIdx.y * 128;
    const int n0 = blockIdx.x * 128;

    __shared__ __align__(16) float sA[128][20];
    __shared__ __align__(16) float sW[16][132];

    const int tid = threadIdx.x;
    const int ty = tid >> 4, tx = tid & 15;

    ull acc2[8][4];
#pragma unroll
    for (int i = 0; i < 8; i++)
#pragma unroll
        for (int p = 0; p < 4; p++) acc2[i][p] = 0ull;

    for (int kt = 0; kt < K; kt += 16) {
#pragma unroll
        for (int u = 0; u < 2; u++) {
            int slot = tid + u * 256;
            int row = slot >> 2, ch = slot & 3;
            int gr = m0 + row;
            float4 v = make_float4(0.f, 0.f, 0.f, 0.f);
            if (gr < NN) v = *(const float4*)(A + (size_t)gr * K + kt + ch * 4);
            *(float4*)&sA[row][ch * 4] = v;
        }
#pragma unroll
        for (int u = 0; u < 2; u++) {
            int slot = tid + u * 256;
            int kk = slot >> 5, nc = (slot & 31) * 4;
            float4 v = *(const float4*)(W + (size_t)(kt + kk) * NHC + n0 + nc);
            *(float4*)&sW[kk][nc] = v;
        }
        __syncthreads();

#pragma unroll
        for (int kk = 0; kk < 16; kk++) {
            float4 w0 = *(float4*)&sW[kk][tx * 8];
            float4 w1 = *(float4*)&sW[kk][tx * 8 + 4];
            ull w2[4] = { pk2(w0.x, w0.y), pk2(w0.z, w0.w),
                          pk2(w1.x, w1.y), pk2(w1.z, w1.w) };
#pragma unroll
            for (int i = 0; i < 8; i++) {
                const float av = sA[ty * 8 + i][kk];
                const ull a2 = pk2(av, av);
#pragma unroll
                for (int p = 0; p < 4; p++)
                    acc2[i][p] = ffma2(a2, w2[p], acc2[i][p]);
            }
        }
        __syncthreads();
    }

    float4 bv0 = *(const float4*)(b + n0 + tx * 8);
    float4 bv1 = *(const float4*)(b + n0 + tx * 8 + 4);
#pragma unroll
    for (int i = 0; i < 8; i++) {
        int gr = m0 + ty * 8 + i;
        if (gr < NN) {
            float a0, a1, a2v, a3, a4, a5, a6, a7;
            upk2(a0, a1, acc2[i][0]);
            upk2(a2v, a3, acc2[i][1]);
            upk2(a4, a5, acc2[i][2]);
            upk2(a6, a7, acc2[i][3]);
            float4 o0 = make_float4(a0 + bv0.x, a1 + bv0.y, a2v + bv0.z, a3 + bv0.w);
            float4 o1 = make_float4(a4 + bv1.x, a5 + bv1.y, a6 + bv1.z, a7 + bv1.w);
            float* op = O + (size_t)gr * NHC + n0 + tx * 8;
            *(float4*)op = o0;
            *(float4*)(op + 4) = o1;
        }
    }
}

// ---------------- pass A: logits -> p = exp(logit), denominator scatter --------
// 64 threads per edge-group; each group processes TWO edges per iteration
// (independent compute + shuffle chains -> 2x ILP, 4 gathers in flight).
// 2-stage software pipeline across iterations.
__global__ __launch_bounds__(128, 5) void k_logits(
    const float* __restrict__ ea,
    const float* __restrict__ We, const float* __restrict__ att)
{
    const int tid   = threadIdx.x;
    const int grp   = tid >> 6;           // 0..1
    const int quad  = tid & 63;           // channel quad
    const int ch0   = quad * 4;
    const int head  = quad >> 4;          // 0..3

    ull wepk[9][2];
#pragma unroll
    for (int k = 0; k < 9; k++) {
        float4 w = *(const float4*)(We + k * NHC + ch0);
        wepk[k][0] = pk2(w.x, w.y);
        wepk[k][1] = pk2(w.z, w.w);
    }
    const float4 att4 = *(const float4*)(att + ch0);

    const int stride = gridDim.x * 4;     // 4 edges per block-iteration
    int eA = blockIdx.x * 4 + grp * 2;    // eA even; eB = eA + 1

    // pipeline prologue: loads for the first edge pair
    int dstA = g_DST[eA],     dstB = g_DST[eA + 1];
    float4 xlA = *(const float4*)(g_XL + (size_t)g_SRC[eA] * NHC + ch0);
    float4 xrA = *(const float4*)(g_XR + (size_t)dstA * NHC + ch0);
    float4 xlB = *(const float4*)(g_XL + (size_t)g_SRC[eA + 1] * NHC + ch0);
    float4 xrB = *(const float4*)(g_XR + (size_t)dstB * NHC + ch0);

    while (eA < NE) {
        // ---- prefetch next pair (clamped; values unused past the end) ----
        const int eA_next = eA + stride;
        const int en = (eA_next < NE) ? eA_next : eA;  // NE even -> en+1 safe
        const int srcAn = __ldg(&g_SRC[en]);
        const int dstAn = __ldg(&g_DST[en]);
        const int srcBn = __ldg(&g_SRC[en + 1]);
        const int dstBn = __ldg(&g_DST[en + 1]);
        const float4 xlAn = *(const float4*)(g_XL + (size_t)srcAn * NHC + ch0);
        const float4 xrAn = *(const float4*)(g_XR + (size_t)dstAn * NHC + ch0);
        const float4 xlBn = *(const float4*)(g_XL + (size_t)srcBn * NHC + ch0);
        const float4 xrBn = *(const float4*)(g_XR + (size_t)dstBn * NHC + ch0);

        // ---- projections (seeded with xl+xr), two independent chains ----
        ull evA01 = fadd2(pk2(xlA.x, xlA.y), pk2(xrA.x, xrA.y));
        ull evA23 = fadd2(pk2(xlA.z, xlA.w), pk2(xrA.z, xrA.w));
        ull evB01 = fadd2(pk2(xlB.x, xlB.y), pk2(xrB.x, xrB.y));
        ull evB23 = fadd2(pk2(xlB.z, xlB.w), pk2(xrB.z, xrB.w));
        const float* eapA = ea + (size_t)eA * 9;
        const float* eapB = eapA + 9;
#pragma unroll
        for (int k = 0; k < 9; k++) {
            const float aA = __ldg(eapA + k);
            const float aB = __ldg(eapB + k);
            const ull aA2 = pk2(aA, aA);
            const ull aB2 = pk2(aB, aB);
            evA01 = ffma2(aA2, wepk[k][0], evA01);
            evA23 = ffma2(aA2, wepk[k][1], evA23);
            evB01 = ffma2(aB2, wepk[k][0], evB01);
            evB23 = ffma2(aB2, wepk[k][1], evB23);
        }
        float ax, ay, az, aw, bx, by, bz, bw;
        upk2(ax, ay, evA01); upk2(az, aw, evA23);
        upk2(bx, by, evB01); upk2(bz, bw, evB23);
        ax = (ax > 0.f) ? ax : 0.2f * ax;  ay = (ay > 0.f) ? ay : 0.2f * ay;
        az = (az > 0.f) ? az : 0.2f * az;  aw = (aw > 0.f) ? aw : 0.2f * aw;
        bx = (bx > 0.f) ? bx : 0.2f * bx;  by = (by > 0.f) ? by : 0.2f * by;
        bz = (bz > 0.f) ? bz : 0.2f * bz;  bw = (bw > 0.f) ? bw : 0.2f * bw;
        float pA = att4.x * ax;
        float pB = att4.x * bx;
        pA = fmaf(att4.y, ay, pA);  pB = fmaf(att4.y, by, pB);
        pA = fmaf(att4.z, az, pA);  pB = fmaf(att4.z, bz, pB);
        pA = fmaf(att4.w, aw, pA);  pB = fmaf(att4.w, bw, pB);

        // interleaved width-16 reductions (independent -> overlap)
        pA += __shfl_down_sync(0xffffffffu, pA, 8, 16);
        pB += __shfl_down_sync(0xffffffffu, pB, 8, 16);
        pA += __shfl_down_sync(0xffffffffu, pA, 4, 16);
        pB += __shfl_down_sync(0xffffffffu, pB, 4, 16);
        pA += __shfl_down_sync(0xffffffffu, pA, 2, 16);
        pB += __shfl_down_sync(0xffffffffu, pB, 2, 16);
        pA += __shfl_down_sync(0xffffffffu, pA, 1, 16);
        pB += __shfl_down_sync(0xffffffffu, pB, 1, 16);

        if ((quad & 15) == 0) {            // reduce root per head
            const float expA = __expf(pA);
            const float expB = __expf(pB);
            g_P[(size_t)eA * NHEADS + head] = expA;
            g_P[(size_t)(eA + 1) * NHEADS + head] = expB;
            atomicAdd(&g_DEN[(size_t)dstA * NHEADS + head], expA);
            atomicAdd(&g_DEN[(size_t)dstB * NHEADS + head], expB);
        }

        // ---- rotate pipeline ----
        eA = eA_next;
        dstA = dstAn;  dstB = dstBn;
        xlA = xlAn;    xrA = xrAn;
        xlB = xlBn;    xrB = xrBn;
    }
}

// ---------------- invert denominators (fold 1/H head-mean in) ----------------
__global__ void k_invden() {
    int i = blockIdx.x * 256 + threadIdx.x;
    if (i < NN * NHEADS) g_DEN[i] = __fdividef(0.25f, g_DEN[i] + 1e-16f);
}

// ---------------- pass B: scatter messages (head-mean folded into alpha) -------
__global__ __launch_bounds__(256) void k_edge_b() {
    const int tid = threadIdx.x;
    const int slot = tid >> 4, q = tid & 15;
    const int e = blockIdx.x * 16 + slot;
    const int src = g_SRC[e];
    const int dst = g_DST[e];

    float al[4];
#pragma unroll
    for (int h = 0; h < 4; h++)
        al[h] = g_P[(size_t)e * 4 + h] * g_DEN[(size_t)dst * 4 + h];

    float4 acc = make_float4(0.f, 0.f, 0.f, 0.f);
    const float* base = g_XL + (size_t)src * NHC + q * 4;
#pragma unroll
    for (int h = 0; h < 4; h++) {
        float4 v = *(const float4*)(base + h * 64);
        acc.x = fmaf(v.x, al[h], acc.x);
        acc.y = fmaf(v.y, al[h], acc.y);
        acc.z = fmaf(v.z, al[h], acc.z);
        acc.w = fmaf(v.w, al[h], acc.w);
    }
    atomicAdd((float4*)(g_ACC + (size_t)dst * 64 + q * 4), acc);
}

// ---------------- node update: bias, gating, leaky-relu + re-zero scratch ------
__global__ void k_node(const float* __restrict__ bias, const float* __restrict__ gates,
                       int layer, float* __restrict__ out) {
    int i = blockIdx.x * 256 + threadIdx.x;   // grid covers exactly NN*NHID
    int c = i & 63;
    float val = g_ACC[i] + bias[c];
    if (layer == 0) {
        g_A[i] = (val > 0.f) ? val : 0.01f * val;
    } else {
        float g = 1.f / (1.f + __expf(-gates[layer - 1]));
        float h = g * val + (1.f - g) * g_A[i];
        if (layer == 1) g_A[i] = (h > 0.f) ? h : 0.01f * h;
        else            out[i] = h;
    }
    // re-zero scratch for the next layer / next kernel_launch call
    g_ACC[i] = 0.f;
    if (i < NN * NHEADS) g_DEN[i] = 0.f;
}

// ---------------- host ----------------
extern "C" void kernel_launch(void* const* d_in, const int* in_sizes, int n_in,
                              void* d_out, int out_size) {
    (void)out_size;
    const float *x = 0, *edge_attr = 0, *gates = 0;
    const float *W32k[4] = {0, 0, 0, 0};  int n32k = 0;   // init_Wl, init_Wr, Wl, Wr
    const float *a256[3] = {0, 0, 0};     int n256 = 0;   // init_bl, init_br, init_att
    const float *a512[3] = {0, 0, 0};     int n512 = 0;   // bl, br, att
    const float *init_We = 0, *WeL = 0, *init_bias = 0, *biasL = 0;
    const void* ei = 0;

    for (int i = 0; i < n_in; i++) {
        const void* p = d_in[i];
        switch (in_sizes[i]) {
            case 6400000: x = (const float*)p; break;
            case 7200000: edge_attr = (const float*)p; break;
            case 1600000: ei = p; break;
            case 3:       gates = (const float*)p; break;
            case 32768:   if (n32k < 4) W32k[n32k++] = (const float*)p; break;
            case 256:     if (n256 < 3) a256[n256++] = (const float*)p; break;
            case 512:     if (n512 < 3) a512[n512++] = (const float*)p; break;
            case 2304:    init_We = (const float*)p; break;
            case 4608:    WeL = (const float*)p; break;
            case 64:      init_bias = (const float*)p; break;
            case 128:     biasL = (const float*)p; break;
            default: break;
        }
    }
    const float *Wl0 = W32k[0], *Wr0 = W32k[1], *WlL = W32k[2], *WrL = W32k[3];
    const float *bl0 = a256[0], *br0 = a256[1], *att0 = a256[2];
    const float *blL = a512[0], *brL = a512[1], *attL = a512[2];
    float* out = (float*)d_out;

    k_convert<<<NE / 256, 256>>>(ei);

    const dim3 gemm_grid(2, (NN + 127) / 128, 2);

    for (int l = 0; l < 3; l++) {
        if (l == 0) {
            k_gemm<128><<<gemm_grid, 256>>>(x, 0, Wl0, bl0, Wr0, br0);
        } else {
            const float* Wl = WlL + (size_t)(l - 1) * 64 * 256;
            const float* Wr = WrL + (size_t)(l - 1) * 64 * 256;
            const float* bl = blL + (size_t)(l - 1) * 256;
            const float* br = brL + (size_t)(l - 1) * 256;
            k_gemm<64><<<gemm_grid, 256>>>(0, 1, Wl, bl, Wr, br);
        }

        const float* We  = l ? (WeL  + (size_t)(l - 1) * 9 * 256) : init_We;
        const float* att = l ? (attL + (size_t)(l - 1) * 256)     : att0;

        k_logits<<<2368, 128>>>(edge_attr, We, att);
        k_invden<<<(NN * NHEADS + 255) / 256, 256>>>();
        k_edge_b<<<NE / 16, 256>>>();

        const float* bias = l ? (biasL + (size_t)(l - 1) * 64) : init_bias;
        k_node<<<NN * NHID / 256, 256>>>(bias, gates, l, out);
    }
}